// round 15
// baseline (speedup 1.0000x reference)
#include <cuda_runtime.h>
#include <cuda.h>
#include <cuda_bf16.h>
#include <cuda_fp16.h>
#include <cstdint>

#define NB 8
#define NL 2048
#define NE 256
#define NH 4
#define ND 64

#define SBATCH ((size_t)NH * NL * NL)   // one batch of scores (fp16): 33.5 MB

// ---------------- scratch (device globals; no allocation allowed) -----------
__device__ __nv_bfloat16 g_xb  [(size_t)NB * NL * NE];        // bf16 x
__device__ __nv_bfloat16 g_wb  [(size_t)2 * NE * NE];         // bf16 w[0:512]
__device__ __nv_bfloat16 g_WgTb[(size_t)NE * NE];             // bf16 Wg^T
__device__ __nv_bfloat16 g_QKb [(size_t)NB * NL * 2 * NE];    // [16384, 512]
__device__ __half        g_S   [2 * SBATCH];                  // double-buffered scores
__device__ __nv_bfloat16 g_Bmb [(size_t)NB * NL * NL];        // head-mean probs
__device__ __nv_bfloat16 g_yT  [(size_t)NB * NE * NL];        // (x @ Wg)^T per b

// ------------------------------- helpers ------------------------------------
__device__ __forceinline__ uint32_t smem_u32(const void* p) {
    uint32_t a;
    asm("{ .reg .u64 t; cvta.to.shared.u64 t, %1; cvt.u32.u64 %0, t; }"
        : "=r"(a) : "l"(p));
    return a;
}

#define MBARRIER_INIT(addr, cnt) \
    asm volatile("mbarrier.init.shared.b64 [%0], %1;" :: "r"(addr), "r"(cnt) : "memory")

#define MBARRIER_EXPECT_TX(addr, bytes) \
    asm volatile("mbarrier.arrive.expect_tx.shared.b64 _, [%0], %1;" \
                 :: "r"(addr), "r"(bytes) : "memory")

#define MBARRIER_WAIT_PARITY(addr, par) do {                                   \
    uint32_t _m = (addr), _p = (par), _d;                                      \
    asm volatile("{\n\t.reg .pred p;\n\t"                                      \
        "mbarrier.try_wait.parity.acquire.cta.shared::cta.b64 p, [%1], %2;\n\t"\
        "selp.b32 %0, 1, 0, p;\n\t}"                                           \
        : "=r"(_d) : "r"(_m), "r"(_p) : "memory");                             \
    if (!_d) {                                                                 \
        asm volatile("{\n\t.reg .pred P1;\n\t"                                 \
        "WL_%=:\n\t"                                                           \
        "mbarrier.try_wait.parity.acquire.cta.shared::cta.b64 P1, [%0], %1, 0x989680;\n\t" \
        "@P1 bra.uni WD_%=;\n\t"                                               \
        "bra.uni WL_%=;\n\t"                                                   \
        "WD_%=:\n\t}" :: "r"(_m), "r"(_p) : "memory");                         \
    }                                                                          \
} while (0)

#define TMA_LOAD_2D(saddr, tmap, cx, cy, mbar)                                 \
    asm volatile("cp.async.bulk.tensor.2d.shared::cta.global.tile.mbarrier::complete_tx::bytes " \
        "[%0], [%1, {%2, %3}], [%4];"                                          \
        :: "r"((uint32_t)(saddr)), "l"(tmap), "r"((int)(cx)), "r"((int)(cy)),  \
           "r"((uint32_t)(mbar)) : "memory")

#define FENCE_ASYNC_SHARED() asm volatile("fence.proxy.async.shared::cta;" ::: "memory")

#define MMA_BF16(d, a, b)                                                      \
    asm volatile("mma.sync.aligned.m16n8k16.row.col.f32.bf16.bf16.f32 "       \
        "{%0,%1,%2,%3}, {%4,%5,%6,%7}, {%8,%9}, {%0,%1,%2,%3};"                \
        : "+f"((d)[0]), "+f"((d)[1]), "+f"((d)[2]), "+f"((d)[3])               \
        : "r"((a)[0]), "r"((a)[1]), "r"((a)[2]), "r"((a)[3]),                  \
          "r"((b)[0]), "r"((b)[1]))

#define LDSM_X4(r0, r1, r2, r3, addr)                                          \
    asm volatile("ldmatrix.sync.aligned.m8n8.x4.shared.b16 {%0,%1,%2,%3}, [%4];" \
        : "=r"(r0), "=r"(r1), "=r"(r2), "=r"(r3) : "r"(addr))

__device__ __forceinline__ void store2(float* p, float a, float b) {
    *(float2*)p = make_float2(a, b);
}
__device__ __forceinline__ void store2(__nv_bfloat16* p, float a, float b) {
    *(__nv_bfloat162*)p = __floats2bfloat162_rn(a, b);
}
__device__ __forceinline__ void store2(__half* p, float a, float b) {
    *(__half2*)p = __floats2half2_rn(a, b);
}

#define STAGES     3
#define STG_BYTES  32768          // A 16KB + B 16KB, dense SW128 tiles
#define GEMM_SMEM  (STAGES * STG_BYTES + 1024 + 64)
// scores path: 2 stages + dedicated fp16 bounce (128 x 136)
#define SC_STAGES  2
#define SC_BOUNCE  (128 * 136 * 2)
#define SC_SMEM    (SC_STAGES * STG_BYTES + SC_BOUNCE + 1024 + 64)

struct Frag { float acc[4][4][4]; };

// one k16 x (4x4) fragment compute step from SW128 tiles
__device__ __forceinline__ void mma_step(
    uint32_t sA, uint32_t sB, int j,
    uint32_t aRow, uint32_t aCol0, uint32_t bRow, uint32_t bCol0, uint32_t xorv,
    Frag& F)
{
    uint32_t af[4][4], bf[4][2];
    const uint32_t ac = (aCol0 + j * 32) ^ xorv;
    const uint32_t bc = (bCol0 + j * 32) ^ xorv;
#pragma unroll
    for (int mt = 0; mt < 4; mt++)
        LDSM_X4(af[mt][0], af[mt][1], af[mt][2], af[mt][3],
                sA + aRow + mt * 2048 + ac);
#pragma unroll
    for (int p = 0; p < 2; p++)
        LDSM_X4(bf[2 * p][0], bf[2 * p][1], bf[2 * p + 1][0], bf[2 * p + 1][1],
                sB + bRow + p * 2048 + bc);
#pragma unroll
    for (int mt = 0; mt < 4; mt++)
#pragma unroll
        for (int nt = 0; nt < 4; nt++)
            MMA_BF16(F.acc[mt][nt], af[mt], bf[nt]);
}

__device__ __forceinline__ void gemm_mainloop(
    uint32_t sal, uint32_t mbb, int tid,
    const CUtensorMap* pA, const CUtensorMap* pB,
    int ary, int acx, int bry, int bcx, int nk,
    uint32_t aRow, uint32_t aCol0, uint32_t bRow, uint32_t bCol0, uint32_t xorv,
    Frag& F)
{
#pragma unroll
    for (int m = 0; m < 4; m++)
#pragma unroll
        for (int n = 0; n < 4; n++)
#pragma unroll
            for (int c = 0; c < 4; c++) F.acc[m][n][c] = 0.f;

    auto issue = [&](int chunk) {
        const int s = chunk % STAGES;
        MBARRIER_EXPECT_TX(mbb + s * 8, (uint32_t)STG_BYTES);
        TMA_LOAD_2D(sal + s * STG_BYTES,         pA, acx + chunk * 64, ary, mbb + s * 8);
        TMA_LOAD_2D(sal + s * STG_BYTES + 16384, pB, bcx + chunk * 64, bry, mbb + s * 8);
    };

    if (tid == 0) {
        issue(0);
        if (nk > 1) issue(1);
    }

    for (int i = 0; i < nk; i++) {
        const int s  = i % STAGES;
        const int ph = (i / STAGES) & 1;

        __syncthreads();
        if (tid == 0 && i + 2 < nk) issue(i + 2);
        MBARRIER_WAIT_PARITY(mbb + s * 8, ph);

        const uint32_t sA = sal + s * STG_BYTES;
        const uint32_t sB = sA + 16384;
#pragma unroll
        for (int j = 0; j < 4; j++)
            mma_step(sA, sB, j, aRow, aCol0, bRow, bCol0, xorv, F);
    }
}

// 16-bit-output epilogue: smem bounce -> coalesced 16B stores
template <typename OutT>
__device__ __forceinline__ void epilogue16(
    char* bounce, int tid, int wr, int wc, int g, int tg,
    OutT* Cz, int ldc, long crow0, int ccol0,
    float alpha, const float* bias, const Frag& F)
{
    OutT* Sb = (OutT*)bounce;            // 128 x 136 halfword
#pragma unroll
    for (int mt = 0; mt < 4; mt++) {
#pragma unroll
        for (int nt = 0; nt < 4; nt++) {
            const int r = wr + mt * 16 + g;
            const int c = wc + nt * 8 + tg * 2;
            float b0 = 0.f, b1 = 0.f;
            if (bias) { b0 = bias[ccol0 + c]; b1 = bias[ccol0 + c + 1]; }
            store2(Sb + (long)r * 136 + c,
                   F.acc[mt][nt][0] * alpha + b0, F.acc[mt][nt][1] * alpha + b1);
            store2(Sb + (long)(r + 8) * 136 + c,
                   F.acc[mt][nt][2] * alpha + b0, F.acc[mt][nt][3] * alpha + b1);
        }
    }
    __syncthreads();
#pragma unroll
    for (int it = 0; it < 8; it++) {
        const int idx = it * 256 + tid;
        const int row = idx >> 4;
        const int c16 = idx & 15;
        float4 v = *(float4*)(Sb + (long)row * 136 + c16 * 8);
        *(float4*)(Cz + (crow0 + row) * ldc + ccol0 + c16 * 8) = v;
    }
}

// ------------------------- generic batched GEMM ------------------------------
template <typename OutT, bool HAS_BIAS>
__global__ __launch_bounds__(256, 2)
void bgemm(const __grid_constant__ CUtensorMap tmA,
           const __grid_constant__ CUtensorMap tmB,
           int a_zo_row, int a_zi_col, int a_col_base,
           int b_zo_row, int b_zi_col, int b_col_base,
           OutT* __restrict__ C, int ldc, long sC,
           int inner, int nk, float alpha, const float* __restrict__ bias)
{
    extern __shared__ char smem[];
    const uint32_t sb0 = smem_u32(smem);
    const uint32_t sal = (sb0 + 1023) & ~1023u;
    const uint32_t mbb = sal + STAGES * STG_BYTES;

    const int tid    = threadIdx.x;
    const int warpId = tid >> 5;
    const int lane   = tid & 31;
    const int g  = lane >> 2;
    const int tg = lane & 3;
    const int wr = (warpId & 1) * 64;
    const int wc = (warpId >> 1) * 32;

    const int z  = blockIdx.z;
    const int zo = z / inner;
    const int zi = z - zo * inner;

    const int ary = zo * a_zo_row + blockIdx.y * 128;
    const int acx = a_col_base + zi * a_zi_col;
    const int bry = zo * b_zo_row + blockIdx.x * 128;
    const int bcx = b_col_base + zi * b_zi_col;

    if (tid == 0) {
#pragma unroll
        for (int s = 0; s < STAGES; s++) MBARRIER_INIT(mbb + s * 8, 1);
        FENCE_ASYNC_SHARED();
    }
    __syncthreads();

    const uint32_t xorv  = (uint32_t)((lane & 7) << 4);
    const uint32_t aRow  = (uint32_t)(wr + (lane & 15)) * 128;
    const uint32_t aCol0 = (uint32_t)((lane >> 4) * 16);
    const uint32_t bRow  = (uint32_t)(wc + (lane & 7) + ((lane >> 4) << 3)) * 128;
    const uint32_t bCol0 = (uint32_t)(((lane >> 3) & 1) * 16);

    Frag F;
    gemm_mainloop(sal, mbb, tid, &tmA, &tmB, ary, acx, bry, bcx, nk,
                  aRow, aCol0, bRow, bCol0, xorv, F);

    __syncthreads();
    char* bounce = smem + (sal - sb0);
    OutT* Cz = C + (long)z * sC;
    const long crow0 = (long)blockIdx.y * 128;
    const int  ccol0 = blockIdx.x * 128;
    const float* bp = HAS_BIAS ? bias : nullptr;

    if (sizeof(OutT) == 2) {
        epilogue16(bounce, tid, wr, wc, g, tg, Cz, ldc, crow0, ccol0, alpha, bp, F);
    } else {
        float* Sb = (float*)bounce;      // 128 x 132 fp32
#pragma unroll
        for (int mt = 0; mt < 4; mt++) {
#pragma unroll
            for (int nt = 0; nt < 4; nt++) {
                const int r = wr + mt * 16 + g;
                const int c = wc + nt * 8 + tg * 2;
                float b0 = 0.f, b1 = 0.f;
                if (HAS_BIAS) { b0 = bias[ccol0 + c]; b1 = bias[ccol0 + c + 1]; }
                *(float2*)(Sb + (long)r * 132 + c) =
                    make_float2(F.acc[mt][nt][0] * alpha + b0, F.acc[mt][nt][1] * alpha + b1);
                *(float2*)(Sb + (long)(r + 8) * 132 + c) =
                    make_float2(F.acc[mt][nt][2] * alpha + b0, F.acc[mt][nt][3] * alpha + b1);
            }
        }
        __syncthreads();
#pragma unroll
        for (int it = 0; it < 16; it++) {
            const int idx = it * 256 + tid;
            const int row = idx >> 5;
            const int c4  = idx & 31;
            float4 v = *(float4*)(Sb + (long)row * 132 + c4 * 4);
            *(float4*)((float*)Cz + (crow0 + row) * ldc + ccol0 + c4 * 4) = v;
        }
    }
}

// ------------- merged QK + yT GEMM (both nk=4, bf16 out) --------------------
__global__ __launch_bounds__(256, 2)
void bgemm_qkyt(const __grid_constant__ CUtensorMap tmXb,
                const __grid_constant__ CUtensorMap tmWb,
                const __grid_constant__ CUtensorMap tmWgT,
                __nv_bfloat16* __restrict__ QKb,
                __nv_bfloat16* __restrict__ yT,
                const float* __restrict__ bia)
{
    extern __shared__ char smem[];
    const uint32_t sb0 = smem_u32(smem);
    const uint32_t sal = (sb0 + 1023) & ~1023u;
    const uint32_t mbb = sal + STAGES * STG_BYTES;

    const int tid    = threadIdx.x;
    const int warpId = tid >> 5;
    const int lane   = tid & 31;
    const int g  = lane >> 2;
    const int tg = lane & 3;
    const int wr = (warpId & 1) * 64;
    const int wc = (warpId >> 1) * 32;

    const int id = blockIdx.x;
    const bool isQK = (id < 512);
    int xt, yt, zb;
    if (isQK) { xt = id & 3;  yt = id >> 2;        zb = 0; }
    else      { int t = id - 512; xt = t & 15; yt = (t >> 4) & 1; zb = t >> 5; }

    const CUtensorMap* pA = isQK ? &tmXb : &tmWgT;
    const CUtensorMap* pB = isQK ? &tmWb : &tmXb;
    const int ary = yt * 128;
    const int bry = (isQK ? 0 : zb * NL) + xt * 128;

    __nv_bfloat16* Cz = isQK ? QKb : (yT + (long)zb * NE * NL);
    const int   ldc   = isQK ? (2 * NE) : NL;
    const float* bias = isQK ? bia : nullptr;

    if (tid == 0) {
#pragma unroll
        for (int s = 0; s < STAGES; s++) MBARRIER_INIT(mbb + s * 8, 1);
        FENCE_ASYNC_SHARED();
    }
    __syncthreads();

    const uint32_t xorv  = (uint32_t)((lane & 7) << 4);
    const uint32_t aRow  = (uint32_t)(wr + (lane & 15)) * 128;
    const uint32_t aCol0 = (uint32_t)((lane >> 4) * 16);
    const uint32_t bRow  = (uint32_t)(wc + (lane & 7) + ((lane >> 4) << 3)) * 128;
    const uint32_t bCol0 = (uint32_t)(((lane >> 3) & 1) * 16);

    Frag F;
    gemm_mainloop(sal, mbb, tid, pA, pB, ary, 0, bry, 0, NE / 64,
                  aRow, aCol0, bRow, bCol0, xorv, F);

    __syncthreads();
    char* bounce = smem + (sal - sb0);
    epilogue16(bounce, tid, wr, wc, g, tg, Cz, ldc,
               (long)yt * 128, xt * 128, 1.f, bias, F);
}

// -------- mixed launch: scores(batch bs) CTAs + pmean(batch bs-1) CTAs ------
// grid.x = [0, nsc) scores tiles (heads-as-chunks nk=4, writes Sw),
//          [nsc, nsc+npm) pmean rows (reads Sr, writes Bm).
// Stream order between launches provides the scores->pmean dependency.
__global__ __launch_bounds__(256, 2)
void sc_pm(const __grid_constant__ CUtensorMap tmQK,
           __half* __restrict__ Sw, const __half* __restrict__ Sr,
           __nv_bfloat16* __restrict__ Bm,
           int bs, int nsc)
{
    extern __shared__ char smem[];
    const int tid = threadIdx.x;
    const int id  = blockIdx.x;

    if (id < nsc) {
        // ---------------- scores tile ----------------
        const uint32_t sb0 = smem_u32(smem);
        const uint32_t sal = (sb0 + 1023) & ~1023u;
        const uint32_t bnc = sal + SC_STAGES * STG_BYTES;
        const uint32_t mbb = bnc + SC_BOUNCE;
        char* bounce = smem + (bnc - sb0);

        const int warpId = tid >> 5;
        const int lane   = tid & 31;
        const int g  = lane >> 2;
        const int tg = lane & 3;
        const int wr = (warpId & 1) * 64;
        const int wc = (warpId >> 1) * 32;

        const int i0 = (id >> 4) * 128;
        const int j0 = (id & 15) * 128;
        const int ary = bs * NL + i0;
        const int bry = bs * NL + j0;

        if (tid == 0) {
#pragma unroll
            for (int s = 0; s < SC_STAGES; s++) MBARRIER_INIT(mbb + s * 8, 1);
            FENCE_ASYNC_SHARED();
        }
        __syncthreads();

        auto issue = [&](int h) {
            const int s = h & 1;
            MBARRIER_EXPECT_TX(mbb + s * 8, (uint32_t)STG_BYTES);
            TMA_LOAD_2D(sal + s * STG_BYTES,         &tmQK, h * 64,       ary, mbb + s * 8);
            TMA_LOAD_2D(sal + s * STG_BYTES + 16384, &tmQK, 256 + h * 64, bry, mbb + s * 8);
        };
        if (tid == 0) { issue(0); issue(1); }

        const uint32_t xorv  = (uint32_t)((lane & 7) << 4);
        const uint32_t aRow  = (uint32_t)(wr + (lane & 15)) * 128;
        const uint32_t aCol0 = (uint32_t)((lane >> 4) * 16);
        const uint32_t bRow  = (uint32_t)(wc + (lane & 7) + ((lane >> 4) << 3)) * 128;
        const uint32_t bCol0 = (uint32_t)(((lane >> 3) & 1) * 16);

        for (int h = 0; h < NH; h++) {
            const int s  = h & 1;
            const int ph = (h >> 1) & 1;
            MBARRIER_WAIT_PARITY(mbb + s * 8, ph);

            Frag F;
#pragma unroll
            for (int m = 0; m < 4; m++)
#pragma unroll
                for (int n = 0; n < 4; n++)
#pragma unroll
                    for (int c = 0; c < 4; c++) F.acc[m][n][c] = 0.f;

            const uint32_t sA = sal + s * STG_BYTES;
            const uint32_t sB = sA + 16384;
#pragma unroll
            for (int j = 0; j < 4; j++)
                mma_step(sA, sB, j, aRow, aCol0, bRow, bCol0, xorv, F);

            __syncthreads();
            if (tid == 0 && h + 2 < NH) issue(h + 2);

            __half* Cz = Sw + ((long)h * NL + i0) * NL;
            epilogue16(bounce, tid, wr, wc, g, tg, Cz, NL,
                       0L, j0, 0.125f, (const float*)nullptr, F);
            __syncthreads();
        }
        return;
    }

    // ---------------- pmean row (batch bs-1, reads Sr) ----------------
    {
        float* red = (float*)smem;        // [8][4]
        const int r    = id - nsc;
        const int wid  = tid >> 5;
        const int lane = tid & 31;

        const __half* base = Sr + (long)r * NL + tid * 8;

        union { float4 f; __half2 hh[4]; } u[NH];
#pragma unroll
        for (int h = 0; h < NH; h++)
            u[h].f = *(const float4*)(base + (long)h * NL * NL);

        float v[NH][8], s[NH];
#pragma unroll
        for (int h = 0; h < NH; h++) {
            float sum = 0.f;
#pragma unroll
            for (int j = 0; j < 4; j++) {
                float2 p = __half22float2(u[h].hh[j]);
                float e0 = __expf(p.x), e1 = __expf(p.y);
                v[h][2 * j] = e0; v[h][2 * j + 1] = e1;
                sum += e0 + e1;
            }
#pragma unroll
            for (int o = 16; o; o >>= 1)
                sum += __shfl_xor_sync(0xffffffffu, sum, o);
            s[h] = sum;
        }
        if (lane < 4) red[wid * 4 + lane] = s[lane];
        __syncthreads();

        float inv[NH];
#pragma unroll
        for (int h = 0; h < NH; h++) {
            float st = red[h];
#pragma unroll
            for (int w2 = 1; w2 < 8; w2++) st += red[w2 * 4 + h];
            inv[h] = 0.25f / st;
        }

        float acc[8];
#pragma unroll
        for (int j = 0; j < 8; j++) {
            acc[j] = v[0][j] * inv[0];
#pragma unroll
            for (int h = 1; h < NH; h++) acc[j] += v[h][j] * inv[h];
        }

        union { float4 f; __nv_bfloat162 hh[4]; } o;
#pragma unroll
        for (int j = 0; j < 4; j++)
            o.hh[j] = __floats2bfloat162_rn(acc[2 * j], acc[2 * j + 1]);
        *(float4*)(Bm + (long)r * NL + tid * 8) = o.f;
    }
}

// ---------------------------------------------------------------------------
// prepasses
__global__ void cvt_bf16_kernel(const float* __restrict__ in,
                                __nv_bfloat16* __restrict__ out, long n)
{
    const long i = ((long)blockIdx.x * blockDim.x + threadIdx.x) * 4;
    if (i < n) {
        float4 v = *(const float4*)(in + i);
        union { uint2 u; __nv_bfloat162 h[2]; } p;
        p.h[0] = __floats2bfloat162_rn(v.x, v.y);
        p.h[1] = __floats2bfloat162_rn(v.z, v.w);
        *(uint2*)(out + i) = p.u;
    }
}

__global__ void transpose_cvt_kernel(const float* __restrict__ in,
                                     __nv_bfloat16* __restrict__ outT,
                                     int R, int Cn)
{
    __shared__ float t[32][33];
    in   += (size_t)blockIdx.z * R * Cn;
    outT += (size_t)blockIdx.z * R * Cn;
    const int r0 = blockIdx.y * 32, c0 = blockIdx.x * 32;
    const int x = threadIdx.x, y = threadIdx.y;
#pragma unroll
    for (int i = 0; i < 32; i += 8)
        t[y + i][x] = in[(long)(r0 + y + i) * Cn + c0 + x];
    __syncthreads();
#pragma unroll
    for (int i = 0; i < 32; i += 8)
        outT[(long)(c0 + y + i) * R + r0 + x] = __float2bfloat16_rn(t[x][y + i]);
}

// ---------------------------------------------------------------------------
typedef CUresult (*encode_fn_t)(
    CUtensorMap*, CUtensorMapDataType, cuuint32_t, void*,
    const cuuint64_t*, const cuuint64_t*, const cuuint32_t*, const cuuint32_t*,
    CUtensorMapInterleave, CUtensorMapSwizzle, CUtensorMapL2promotion,
    CUtensorMapFloatOOBfill);

static void make_map(encode_fn_t enc, CUtensorMap* m, void* ptr, long rows, long cols)
{
    cuuint64_t dims[2]    = {(cuuint64_t)cols, (cuuint64_t)rows};
    cuuint64_t strides[1] = {(cuuint64_t)cols * 2};
    cuuint32_t box[2]     = {64u, 128u};
    cuuint32_t es[2]      = {1u, 1u};
    enc(m, CU_TENSOR_MAP_DATA_TYPE_BFLOAT16, 2, ptr, dims, strides, box, es,
        CU_TENSOR_MAP_INTERLEAVE_NONE, CU_TENSOR_MAP_SWIZZLE_128B,
        CU_TENSOR_MAP_L2_PROMOTION_L2_128B, CU_TENSOR_MAP_FLOAT_OOB_FILL_NONE);
}

extern "C" void kernel_launch(void* const* d_in, const int* in_sizes, int n_in,
                              void* d_out, int out_size)
{
    (void)in_sizes; (void)n_in; (void)out_size;
    const float* x   = (const float*)d_in[0];
    const float* w   = (const float*)d_in[1];
    const float* bia = (const float*)d_in[2];
    const float* Wg  = (const float*)d_in[3];
    const float* Bg  = (const float*)d_in[4];
    float* out = (float*)d_out;

    __nv_bfloat16 *xb, *wb, *WgTb, *QKb, *Bmb, *yT;
    __half* S;
    cudaGetSymbolAddress((void**)&xb,   g_xb);
    cudaGetSymbolAddress((void**)&wb,   g_wb);
    cudaGetSymbolAddress((void**)&WgTb, g_WgTb);
    cudaGetSymbolAddress((void**)&QKb,  g_QKb);
    cudaGetSymbolAddress((void**)&S,    g_S);
    cudaGetSymbolAddress((void**)&Bmb,  g_Bmb);
    cudaGetSymbolAddress((void**)&yT,   g_yT);

    encode_fn_t enc = nullptr;
    {
        void* p = nullptr;
        cudaDriverEntryPointQueryResult st;
        cudaGetDriverEntryPoint("cuTensorMapEncodeTiled", &p, cudaEnableDefault, &st);
        enc = (encode_fn_t)p;
    }

    CUtensorMap m_xb, m_wb, m_WgTb, m_QKb, m_Bmb, m_yT;
    make_map(enc, &m_xb,   xb,   (long)NB * NL, NE);
    make_map(enc, &m_wb,   wb,   2 * NE,        NE);
    make_map(enc, &m_WgTb, WgTb, NE,            NE);
    make_map(enc, &m_QKb,  QKb,  (long)NB * NL, 2 * NE);
    make_map(enc, &m_Bmb,  Bmb,  (long)NB * NL, NL);
    make_map(enc, &m_yT,   yT,   (long)NB * NE, NL);

    cudaFuncSetAttribute((const void*)bgemm_qkyt,
                         cudaFuncAttributeMaxDynamicSharedMemorySize, GEMM_SMEM);
    cudaFuncSetAttribute((const void*)sc_pm,
                         cudaFuncAttributeMaxDynamicSharedMemorySize, SC_SMEM);
    cudaFuncSetAttribute((const void*)bgemm<float, true>,
                         cudaFuncAttributeMaxDynamicSharedMemorySize, GEMM_SMEM);

    // 0) bf16 operand prep
    {
        const long nx = (long)NB * NL * NE;
        cvt_bf16_kernel<<<(int)(nx / 4 / 256), 256>>>(x, xb, nx);
        const long nw = (long)2 * NE * NE;
        cvt_bf16_kernel<<<(int)((nw / 4 + 255) / 256), 256>>>(w, wb, nw);
        transpose_cvt_kernel<<<dim3(NE / 32, NE / 32, 1), dim3(32, 8)>>>(Wg, WgTb, NE, NE);
    }

    // 1+2) merged: QK = xb @ wb^T + bias  AND  yT[b] = WgT @ x[b]^T
    bgemm_qkyt<<<768, 256, GEMM_SMEM>>>(m_xb, m_wb, m_WgTb, QKb, yT, bia);

    // 3+4) software-pipelined scores/pmean: launch t does scores(batch t)
    //      and pmean(batch t-1) concurrently; double-buffered L2-resident S.
    for (int t = 0; t <= NB; t++) {
        const int bs  = (t < NB) ? t : -1;
        const int bp  = t - 1;
        const int nsc = (bs >= 0) ? 256 : 0;
        const int npm = (bp >= 0) ? NL : 0;
        sc_pm<<<nsc + npm, 256, SC_SMEM>>>(
            m_QKb,
            S + (size_t)(t & 1) * SBATCH,
            S + (size_t)((t + 1) & 1) * SBATCH,
            (bp >= 0) ? (Bmb + (long)bp * NL * NL) : nullptr,
            bs, nsc);
    }

    // 5) out[b] = Bm[b] @ yT[b]^T + Bg   [2048 x 256] x8, K=2048 (nk=32)
    bgemm<float, true><<<dim3(2, 16, NB), 256, GEMM_SMEM>>>(
        m_Bmb, m_yT,
        NL, 0, 0,   NE, 0, 0,
        out, NE, (long)NL * NE,
        1, NL / 64, 1.f, Bg);
}

// round 16
// speedup vs baseline: 1.1756x; 1.1756x over previous
#include <cuda_runtime.h>
#include <cuda.h>
#include <cuda_bf16.h>
#include <cuda_fp16.h>
#include <cstdint>

#define NB 8
#define NL 2048
#define NE 256
#define NH 4
#define ND 64

// ---------------- scratch (device globals; no allocation allowed) -----------
__device__ __nv_bfloat16 g_xb  [(size_t)NB * NL * NE];        // bf16 x
__device__ __nv_bfloat16 g_wb  [(size_t)2 * NE * NE];         // bf16 w[0:512]
__device__ __nv_bfloat16 g_WgTb[(size_t)NE * NE];             // bf16 Wg^T
__device__ __nv_bfloat16 g_QKb [(size_t)NB * NL * 2 * NE];    // [16384, 512]
__device__ __half        g_S   [(size_t)NB * NH * NL * NL];   // raw scores fp16
__device__ __nv_bfloat16 g_Bmb [(size_t)NB * NL * NL];        // head-mean probs
__device__ __nv_bfloat16 g_yT  [(size_t)NB * NE * NL];        // (x @ Wg)^T per b

// ------------------------------- helpers ------------------------------------
__device__ __forceinline__ uint32_t smem_u32(const void* p) {
    uint32_t a;
    asm("{ .reg .u64 t; cvta.to.shared.u64 t, %1; cvt.u32.u64 %0, t; }"
        : "=r"(a) : "l"(p));
    return a;
}

#define MBARRIER_INIT(addr, cnt) \
    asm volatile("mbarrier.init.shared.b64 [%0], %1;" :: "r"(addr), "r"(cnt) : "memory")

#define MBARRIER_EXPECT_TX(addr, bytes) \
    asm volatile("mbarrier.arrive.expect_tx.shared.b64 _, [%0], %1;" \
                 :: "r"(addr), "r"(bytes) : "memory")

#define MBARRIER_WAIT_PARITY(addr, par) do {                                   \
    uint32_t _m = (addr), _p = (par), _d;                                      \
    asm volatile("{\n\t.reg .pred p;\n\t"                                      \
        "mbarrier.try_wait.parity.acquire.cta.shared::cta.b64 p, [%1], %2;\n\t"\
        "selp.b32 %0, 1, 0, p;\n\t}"                                           \
        : "=r"(_d) : "r"(_m), "r"(_p) : "memory");                             \
    if (!_d) {                                                                 \
        asm volatile("{\n\t.reg .pred P1;\n\t"                                 \
        "WL_%=:\n\t"                                                           \
        "mbarrier.try_wait.parity.acquire.cta.shared::cta.b64 P1, [%0], %1, 0x989680;\n\t" \
        "@P1 bra.uni WD_%=;\n\t"                                               \
        "bra.uni WL_%=;\n\t"                                                   \
        "WD_%=:\n\t}" :: "r"(_m), "r"(_p) : "memory");                         \
    }                                                                          \
} while (0)

#define TMA_LOAD_2D(saddr, tmap, cx, cy, mbar)                                 \
    asm volatile("cp.async.bulk.tensor.2d.shared::cta.global.tile.mbarrier::complete_tx::bytes " \
        "[%0], [%1, {%2, %3}], [%4];"                                          \
        :: "r"((uint32_t)(saddr)), "l"(tmap), "r"((int)(cx)), "r"((int)(cy)),  \
           "r"((uint32_t)(mbar)) : "memory")

#define FENCE_ASYNC_SHARED() asm volatile("fence.proxy.async.shared::cta;" ::: "memory")

#define MMA_BF16(d, a, b)                                                      \
    asm volatile("mma.sync.aligned.m16n8k16.row.col.f32.bf16.bf16.f32 "       \
        "{%0,%1,%2,%3}, {%4,%5,%6,%7}, {%8,%9}, {%0,%1,%2,%3};"                \
        : "+f"((d)[0]), "+f"((d)[1]), "+f"((d)[2]), "+f"((d)[3])               \
        : "r"((a)[0]), "r"((a)[1]), "r"((a)[2]), "r"((a)[3]),                  \
          "r"((b)[0]), "r"((b)[1]))

#define LDSM_X4(r0, r1, r2, r3, addr)                                          \
    asm volatile("ldmatrix.sync.aligned.m8n8.x4.shared.b16 {%0,%1,%2,%3}, [%4];" \
        : "=r"(r0), "=r"(r1), "=r"(r2), "=r"(r3) : "r"(addr))

__device__ __forceinline__ void store2(float* p, float a, float b) {
    *(float2*)p = make_float2(a, b);
}
__device__ __forceinline__ void store2(__nv_bfloat16* p, float a, float b) {
    *(__nv_bfloat162*)p = __floats2bfloat162_rn(a, b);
}
__device__ __forceinline__ void store2(__half* p, float a, float b) {
    *(__half2*)p = __floats2half2_rn(a, b);
}

#define STAGES     3
#define STG_BYTES  32768          // A 16KB + B 16KB, dense SW128 tiles
#define GEMM_SMEM  (STAGES * STG_BYTES + 1024 + 64)
// scores kernel: 2 stages + dedicated fp16 bounce (128 x 136)
#define SC_STAGES  2
#define SC_BOUNCE  (128 * 136 * 2)
#define SC_SMEM    (SC_STAGES * STG_BYTES + SC_BOUNCE + 1024 + 64)

struct Frag { float acc[4][4][4]; };

// one k16 x (4x4) fragment compute step from SW128 tiles
__device__ __forceinline__ void mma_step(
    uint32_t sA, uint32_t sB, int j,
    uint32_t aRow, uint32_t aCol0, uint32_t bRow, uint32_t bCol0, uint32_t xorv,
    Frag& F)
{
    uint32_t af[4][4], bf[4][2];
    const uint32_t ac = (aCol0 + j * 32) ^ xorv;
    const uint32_t bc = (bCol0 + j * 32) ^ xorv;
#pragma unroll
    for (int mt = 0; mt < 4; mt++)
        LDSM_X4(af[mt][0], af[mt][1], af[mt][2], af[mt][3],
                sA + aRow + mt * 2048 + ac);
#pragma unroll
    for (int p = 0; p < 2; p++)
        LDSM_X4(bf[2 * p][0], bf[2 * p][1], bf[2 * p + 1][0], bf[2 * p + 1][1],
                sB + bRow + p * 2048 + bc);
#pragma unroll
    for (int mt = 0; mt < 4; mt++)
#pragma unroll
        for (int nt = 0; nt < 4; nt++)
            MMA_BF16(F.acc[mt][nt], af[mt], bf[nt]);
}

__device__ __forceinline__ void gemm_mainloop(
    uint32_t sal, uint32_t mbb, int tid,
    const CUtensorMap* pA, const CUtensorMap* pB,
    int ary, int acx, int bry, int bcx, int nk,
    uint32_t aRow, uint32_t aCol0, uint32_t bRow, uint32_t bCol0, uint32_t xorv,
    Frag& F)
{
#pragma unroll
    for (int m = 0; m < 4; m++)
#pragma unroll
        for (int n = 0; n < 4; n++)
#pragma unroll
            for (int c = 0; c < 4; c++) F.acc[m][n][c] = 0.f;

    auto issue = [&](int chunk) {
        const int s = chunk % STAGES;
        MBARRIER_EXPECT_TX(mbb + s * 8, (uint32_t)STG_BYTES);
        TMA_LOAD_2D(sal + s * STG_BYTES,         pA, acx + chunk * 64, ary, mbb + s * 8);
        TMA_LOAD_2D(sal + s * STG_BYTES + 16384, pB, bcx + chunk * 64, bry, mbb + s * 8);
    };

    if (tid == 0) {
        issue(0);
        if (nk > 1) issue(1);
    }

    for (int i = 0; i < nk; i++) {
        const int s  = i % STAGES;
        const int ph = (i / STAGES) & 1;

        __syncthreads();
        if (tid == 0 && i + 2 < nk) issue(i + 2);
        MBARRIER_WAIT_PARITY(mbb + s * 8, ph);

        const uint32_t sA = sal + s * STG_BYTES;
        const uint32_t sB = sA + 16384;
#pragma unroll
        for (int j = 0; j < 4; j++)
            mma_step(sA, sB, j, aRow, aCol0, bRow, bCol0, xorv, F);
    }
}

// 16-bit-output epilogue: smem bounce -> coalesced 16B stores
template <typename OutT>
__device__ __forceinline__ void epilogue16(
    char* bounce, int tid, int wr, int wc, int g, int tg,
    OutT* Cz, int ldc, long crow0, int ccol0,
    float alpha, const float* bias, const Frag& F)
{
    OutT* Sb = (OutT*)bounce;            // 128 x 136 halfword
#pragma unroll
    for (int mt = 0; mt < 4; mt++) {
#pragma unroll
        for (int nt = 0; nt < 4; nt++) {
            const int r = wr + mt * 16 + g;
            const int c = wc + nt * 8 + tg * 2;
            float b0 = 0.f, b1 = 0.f;
            if (bias) { b0 = bias[ccol0 + c]; b1 = bias[ccol0 + c + 1]; }
            store2(Sb + (long)r * 136 + c,
                   F.acc[mt][nt][0] * alpha + b0, F.acc[mt][nt][1] * alpha + b1);
            store2(Sb + (long)(r + 8) * 136 + c,
                   F.acc[mt][nt][2] * alpha + b0, F.acc[mt][nt][3] * alpha + b1);
        }
    }
    __syncthreads();
#pragma unroll
    for (int it = 0; it < 8; it++) {
        const int idx = it * 256 + tid;
        const int row = idx >> 4;
        const int c16 = idx & 15;
        float4 v = *(float4*)(Sb + (long)row * 136 + c16 * 8);
        *(float4*)(Cz + (crow0 + row) * ldc + ccol0 + c16 * 8) = v;
    }
}

// ------------------------- generic batched GEMM ------------------------------
template <typename OutT, bool HAS_BIAS>
__global__ __launch_bounds__(256, 2)
void bgemm(const __grid_constant__ CUtensorMap tmA,
           const __grid_constant__ CUtensorMap tmB,
           int a_zo_row, int a_zi_col, int a_col_base,
           int b_zo_row, int b_zi_col, int b_col_base,
           OutT* __restrict__ C, int ldc, long sC,
           int inner, int nk, float alpha, const float* __restrict__ bias)
{
    extern __shared__ char smem[];
    const uint32_t sb0 = smem_u32(smem);
    const uint32_t sal = (sb0 + 1023) & ~1023u;
    const uint32_t mbb = sal + STAGES * STG_BYTES;

    const int tid    = threadIdx.x;
    const int warpId = tid >> 5;
    const int lane   = tid & 31;
    const int g  = lane >> 2;
    const int tg = lane & 3;
    const int wr = (warpId & 1) * 64;
    const int wc = (warpId >> 1) * 32;

    const int z  = blockIdx.z;
    const int zo = z / inner;
    const int zi = z - zo * inner;

    const int ary = zo * a_zo_row + blockIdx.y * 128;
    const int acx = a_col_base + zi * a_zi_col;
    const int bry = zo * b_zo_row + blockIdx.x * 128;
    const int bcx = b_col_base + zi * b_zi_col;

    if (tid == 0) {
#pragma unroll
        for (int s = 0; s < STAGES; s++) MBARRIER_INIT(mbb + s * 8, 1);
        FENCE_ASYNC_SHARED();
    }
    __syncthreads();

    const uint32_t xorv  = (uint32_t)((lane & 7) << 4);
    const uint32_t aRow  = (uint32_t)(wr + (lane & 15)) * 128;
    const uint32_t aCol0 = (uint32_t)((lane >> 4) * 16);
    const uint32_t bRow  = (uint32_t)(wc + (lane & 7) + ((lane >> 4) << 3)) * 128;
    const uint32_t bCol0 = (uint32_t)(((lane >> 3) & 1) * 16);

    Frag F;
    gemm_mainloop(sal, mbb, tid, &tmA, &tmB, ary, acx, bry, bcx, nk,
                  aRow, aCol0, bRow, bCol0, xorv, F);

    __syncthreads();
    char* bounce = smem + (sal - sb0);
    OutT* Cz = C + (long)z * sC;
    const long crow0 = (long)blockIdx.y * 128;
    const int  ccol0 = blockIdx.x * 128;
    const float* bp = HAS_BIAS ? bias : nullptr;

    if (sizeof(OutT) == 2) {
        epilogue16(bounce, tid, wr, wc, g, tg, Cz, ldc, crow0, ccol0, alpha, bp, F);
    } else {
        float* Sb = (float*)bounce;      // 128 x 132 fp32
#pragma unroll
        for (int mt = 0; mt < 4; mt++) {
#pragma unroll
            for (int nt = 0; nt < 4; nt++) {
                const int r = wr + mt * 16 + g;
                const int c = wc + nt * 8 + tg * 2;
                float b0 = 0.f, b1 = 0.f;
                if (HAS_BIAS) { b0 = bias[ccol0 + c]; b1 = bias[ccol0 + c + 1]; }
                *(float2*)(Sb + (long)r * 132 + c) =
                    make_float2(F.acc[mt][nt][0] * alpha + b0, F.acc[mt][nt][1] * alpha + b1);
                *(float2*)(Sb + (long)(r + 8) * 132 + c) =
                    make_float2(F.acc[mt][nt][2] * alpha + b0, F.acc[mt][nt][3] * alpha + b1);
            }
        }
        __syncthreads();
#pragma unroll
        for (int it = 0; it < 16; it++) {
            const int idx = it * 256 + tid;
            const int row = idx >> 5;
            const int c4  = idx & 31;
            float4 v = *(float4*)(Sb + (long)row * 132 + c4 * 4);
            *(float4*)((float*)Cz + (crow0 + row) * ldc + ccol0 + c4 * 4) = v;
        }
    }
}

// ------------- merged QK + yT GEMM (both nk=4, bf16 out) --------------------
__global__ __launch_bounds__(256, 2)
void bgemm_qkyt(const __grid_constant__ CUtensorMap tmXb,
                const __grid_constant__ CUtensorMap tmWb,
                const __grid_constant__ CUtensorMap tmWgT,
                __nv_bfloat16* __restrict__ QKb,
                __nv_bfloat16* __restrict__ yT,
                const float* __restrict__ bia)
{
    extern __shared__ char smem[];
    const uint32_t sb0 = smem_u32(smem);
    const uint32_t sal = (sb0 + 1023) & ~1023u;
    const uint32_t mbb = sal + STAGES * STG_BYTES;

    const int tid    = threadIdx.x;
    const int warpId = tid >> 5;
    const int lane   = tid & 31;
    const int g  = lane >> 2;
    const int tg = lane & 3;
    const int wr = (warpId & 1) * 64;
    const int wc = (warpId >> 1) * 32;

    const int id = blockIdx.x;
    const bool isQK = (id < 512);
    int xt, yt, zb;
    if (isQK) { xt = id & 3;  yt = id >> 2;        zb = 0; }
    else      { int t = id - 512; xt = t & 15; yt = (t >> 4) & 1; zb = t >> 5; }

    const CUtensorMap* pA = isQK ? &tmXb : &tmWgT;
    const CUtensorMap* pB = isQK ? &tmWb : &tmXb;
    const int ary = yt * 128;
    const int bry = (isQK ? 0 : zb * NL) + xt * 128;

    __nv_bfloat16* Cz = isQK ? QKb : (yT + (long)zb * NE * NL);
    const int   ldc   = isQK ? (2 * NE) : NL;
    const float* bias = isQK ? bia : nullptr;

    if (tid == 0) {
#pragma unroll
        for (int s = 0; s < STAGES; s++) MBARRIER_INIT(mbb + s * 8, 1);
        FENCE_ASYNC_SHARED();
    }
    __syncthreads();

    const uint32_t xorv  = (uint32_t)((lane & 7) << 4);
    const uint32_t aRow  = (uint32_t)(wr + (lane & 15)) * 128;
    const uint32_t aCol0 = (uint32_t)((lane >> 4) * 16);
    const uint32_t bRow  = (uint32_t)(wc + (lane & 7) + ((lane >> 4) << 3)) * 128;
    const uint32_t bCol0 = (uint32_t)(((lane >> 3) & 1) * 16);

    Frag F;
    gemm_mainloop(sal, mbb, tid, pA, pB, ary, 0, bry, 0, NE / 64,
                  aRow, aCol0, bRow, bCol0, xorv, F);

    __syncthreads();
    char* bounce = smem + (sal - sb0);
    epilogue16(bounce, tid, wr, wc, g, tg, Cz, ldc,
               (long)yt * 128, xt * 128, 1.f, bias, F);
}

// ------------------ scores GEMM: heads-as-chunks (nk=4) ----------------------
// grid (16 j-tiles, 16 i-tiles, NB). Per chunk h: S[b,h] tile = 0.125*q_h@k_h^T.
// 2-stage pipeline + dedicated bounce; per-chunk epilogue overlaps next TMA.
__global__ __launch_bounds__(256, 2)
void bgemm_scores(const __grid_constant__ CUtensorMap tmQK,
                  __half* __restrict__ S)
{
    extern __shared__ char smem[];
    const uint32_t sb0 = smem_u32(smem);
    const uint32_t sal = (sb0 + 1023) & ~1023u;
    const uint32_t bnc = sal + SC_STAGES * STG_BYTES;
    const uint32_t mbb = bnc + SC_BOUNCE;
    char* bounce = smem + (bnc - sb0);

    const int tid    = threadIdx.x;
    const int warpId = tid >> 5;
    const int lane   = tid & 31;
    const int g  = lane >> 2;
    const int tg = lane & 3;
    const int wr = (warpId & 1) * 64;
    const int wc = (warpId >> 1) * 32;

    const int b  = blockIdx.z;
    const int i0 = blockIdx.y * 128;
    const int j0 = blockIdx.x * 128;
    const int ary = b * NL + i0;
    const int bry = b * NL + j0;

    if (tid == 0) {
#pragma unroll
        for (int s = 0; s < SC_STAGES; s++) MBARRIER_INIT(mbb + s * 8, 1);
        FENCE_ASYNC_SHARED();
    }
    __syncthreads();

    auto issue = [&](int h) {
        const int s = h & 1;
        MBARRIER_EXPECT_TX(mbb + s * 8, (uint32_t)STG_BYTES);
        TMA_LOAD_2D(sal + s * STG_BYTES,         &tmQK, h * 64,       ary, mbb + s * 8);
        TMA_LOAD_2D(sal + s * STG_BYTES + 16384, &tmQK, 256 + h * 64, bry, mbb + s * 8);
    };

    if (tid == 0) { issue(0); issue(1); }

    const uint32_t xorv  = (uint32_t)((lane & 7) << 4);
    const uint32_t aRow  = (uint32_t)(wr + (lane & 15)) * 128;
    const uint32_t aCol0 = (uint32_t)((lane >> 4) * 16);
    const uint32_t bRow  = (uint32_t)(wc + (lane & 7) + ((lane >> 4) << 3)) * 128;
    const uint32_t bCol0 = (uint32_t)(((lane >> 3) & 1) * 16);

    for (int h = 0; h < NH; h++) {
        const int s  = h & 1;
        const int ph = (h >> 1) & 1;
        MBARRIER_WAIT_PARITY(mbb + s * 8, ph);

        Frag F;
#pragma unroll
        for (int m = 0; m < 4; m++)
#pragma unroll
            for (int n = 0; n < 4; n++)
#pragma unroll
                for (int c = 0; c < 4; c++) F.acc[m][n][c] = 0.f;

        const uint32_t sA = sal + s * STG_BYTES;
        const uint32_t sB = sA + 16384;
#pragma unroll
        for (int j = 0; j < 4; j++)
            mma_step(sA, sB, j, aRow, aCol0, bRow, bCol0, xorv, F);

        __syncthreads();                 // all warps done reading stage s
        if (tid == 0 && h + 2 < NH) issue(h + 2);

        // per-chunk epilogue into dedicated bounce (overlaps stage refill)
        __half* Cz = S + ((long)(b * NH + h) * NL + i0) * NL;
        epilogue16(bounce, tid, wr, wc, g, tg, Cz, NL,
                   0L, j0, 0.125f, (const float*)nullptr, F);
        __syncthreads();                 // bounce reusable next chunk
    }
}

// ---------------------------------------------------------------------------
// head-mean softmax from raw fp16 scores; streaming reads.
__global__ __launch_bounds__(256)
void pmean_kernel(const __half* __restrict__ S, __nv_bfloat16* __restrict__ Bm)
{
    __shared__ float red[8][4];
    const int bi   = blockIdx.x;
    const int b    = bi >> 11;
    const int i    = bi & 2047;
    const int tid  = threadIdx.x;
    const int wid  = tid >> 5;
    const int lane = tid & 31;

    const __half* base = S + ((long)b * NH * NL + i) * NL + tid * 8;

    union F4H { float4 f; __half2 hh[4]; } u[NH];
#pragma unroll
    for (int h = 0; h < NH; h++)
        u[h].f = __ldcs((const float4*)(base + (long)h * NL * NL));

    float v[NH][8], s[NH];
#pragma unroll
    for (int h = 0; h < NH; h++) {
        float sum = 0.f;
#pragma unroll
        for (int j = 0; j < 4; j++) {
            float2 p = __half22float2(u[h].hh[j]);
            float e0 = __expf(p.x), e1 = __expf(p.y);
            v[h][2 * j] = e0; v[h][2 * j + 1] = e1;
            sum += e0 + e1;
        }
#pragma unroll
        for (int o = 16; o; o >>= 1)
            sum += __shfl_xor_sync(0xffffffffu, sum, o);
        s[h] = sum;
    }
    if (lane < 4) red[wid][lane] = s[lane];
    __syncthreads();

    float inv[NH];
#pragma unroll
    for (int h = 0; h < NH; h++) {
        float st = red[0][h];
#pragma unroll
        for (int w = 1; w < 8; w++) st += red[w][h];
        inv[h] = 0.25f / st;
    }

    float acc[8];
#pragma unroll
    for (int j = 0; j < 8; j++) {
        acc[j] = v[0][j] * inv[0];
#pragma unroll
        for (int h = 1; h < NH; h++) acc[j] += v[h][j] * inv[h];
    }

    union { float4 f; __nv_bfloat162 hh[4]; } o;
#pragma unroll
    for (int j = 0; j < 4; j++)
        o.hh[j] = __floats2bfloat162_rn(acc[2 * j], acc[2 * j + 1]);
    *(float4*)(Bm + (long)bi * NL + tid * 8) = o.f;
}

// ---------------------------------------------------------------------------
// fused prep: one launch covering x-convert, w-convert, WgT transpose.
// grid.x: [0,4096) x cvt ; [4096,4224) w cvt ; [4224,4288) WgT transpose.
__global__ __launch_bounds__(256)
void prep_kernel(const float* __restrict__ x,  __nv_bfloat16* __restrict__ xb,
                 const float* __restrict__ w,  __nv_bfloat16* __restrict__ wb,
                 const float* __restrict__ Wg, __nv_bfloat16* __restrict__ WgTb)
{
    __shared__ float t[32][33];
    const int id  = blockIdx.x;
    const int tid = threadIdx.x;

    if (id < 4096) {
        const long i = ((long)id * 256 + tid) * 4;       // covers 8*2048*256 floats
        float4 v = *(const float4*)(x + i);
        union { uint2 u; __nv_bfloat162 h[2]; } p;
        p.h[0] = __floats2bfloat162_rn(v.x, v.y);
        p.h[1] = __floats2bfloat162_rn(v.z, v.w);
        *(uint2*)(xb + i) = p.u;
    } else if (id < 4224) {
        const long i = ((long)(id - 4096) * 256 + tid) * 4;  // covers 2*256*256 floats
        float4 v = *(const float4*)(w + i);
        union { uint2 u; __nv_bfloat162 h[2]; } p;
        p.h[0] = __floats2bfloat162_rn(v.x, v.y);
        p.h[1] = __floats2bfloat162_rn(v.z, v.w);
        *(uint2*)(wb + i) = p.u;
    } else {
        const int bidx = id - 4224;                      // 8x8 tiles of 32x32
        const int c0 = (bidx & 7) * 32;
        const int r0 = (bidx >> 3) * 32;
        const int xx = tid & 31, yy = tid >> 5;          // (32, 8)
#pragma unroll
        for (int i = 0; i < 32; i += 8)
            t[yy + i][xx] = Wg[(long)(r0 + yy + i) * NE + c0 + xx];
        __syncthreads();
#pragma unroll
        for (int i = 0; i < 32; i += 8)
            WgTb[(long)(c0 + yy + i) * NE + r0 + xx] = __float2bfloat16_rn(t[xx][yy + i]);
    }
}

// ---------------------------------------------------------------------------
typedef CUresult (*encode_fn_t)(
    CUtensorMap*, CUtensorMapDataType, cuuint32_t, void*,
    const cuuint64_t*, const cuuint64_t*, const cuuint32_t*, const cuuint32_t*,
    CUtensorMapInterleave, CUtensorMapSwizzle, CUtensorMapL2promotion,
    CUtensorMapFloatOOBfill);

static void make_map(encode_fn_t enc, CUtensorMap* m, void* ptr, long rows, long cols)
{
    cuuint64_t dims[2]    = {(cuuint64_t)cols, (cuuint64_t)rows};
    cuuint64_t strides[1] = {(cuuint64_t)cols * 2};
    cuuint32_t box[2]     = {64u, 128u};
    cuuint32_t es[2]      = {1u, 1u};
    enc(m, CU_TENSOR_MAP_DATA_TYPE_BFLOAT16, 2, ptr, dims, strides, box, es,
        CU_TENSOR_MAP_INTERLEAVE_NONE, CU_TENSOR_MAP_SWIZZLE_128B,
        CU_TENSOR_MAP_L2_PROMOTION_L2_128B, CU_TENSOR_MAP_FLOAT_OOB_FILL_NONE);
}

extern "C" void kernel_launch(void* const* d_in, const int* in_sizes, int n_in,
                              void* d_out, int out_size)
{
    (void)in_sizes; (void)n_in; (void)out_size;
    const float* x   = (const float*)d_in[0];
    const float* w   = (const float*)d_in[1];
    const float* bia = (const float*)d_in[2];
    const float* Wg  = (const float*)d_in[3];
    const float* Bg  = (const float*)d_in[4];
    float* out = (float*)d_out;

    __nv_bfloat16 *xb, *wb, *WgTb, *QKb, *Bmb, *yT;
    __half* S;
    cudaGetSymbolAddress((void**)&xb,   g_xb);
    cudaGetSymbolAddress((void**)&wb,   g_wb);
    cudaGetSymbolAddress((void**)&WgTb, g_WgTb);
    cudaGetSymbolAddress((void**)&QKb,  g_QKb);
    cudaGetSymbolAddress((void**)&S,    g_S);
    cudaGetSymbolAddress((void**)&Bmb,  g_Bmb);
    cudaGetSymbolAddress((void**)&yT,   g_yT);

    encode_fn_t enc = nullptr;
    {
        void* p = nullptr;
        cudaDriverEntryPointQueryResult st;
        cudaGetDriverEntryPoint("cuTensorMapEncodeTiled", &p, cudaEnableDefault, &st);
        enc = (encode_fn_t)p;
    }

    CUtensorMap m_xb, m_wb, m_WgTb, m_QKb, m_Bmb, m_yT;
    make_map(enc, &m_xb,   xb,   (long)NB * NL, NE);
    make_map(enc, &m_wb,   wb,   2 * NE,        NE);
    make_map(enc, &m_WgTb, WgTb, NE,            NE);
    make_map(enc, &m_QKb,  QKb,  (long)NB * NL, 2 * NE);
    make_map(enc, &m_Bmb,  Bmb,  (long)NB * NL, NL);
    make_map(enc, &m_yT,   yT,   (long)NB * NE, NL);

    cudaFuncSetAttribute((const void*)bgemm_qkyt,
                         cudaFuncAttributeMaxDynamicSharedMemorySize, GEMM_SMEM);
    cudaFuncSetAttribute((const void*)bgemm_scores,
                         cudaFuncAttributeMaxDynamicSharedMemorySize, SC_SMEM);
    cudaFuncSetAttribute((const void*)bgemm<float, true>,
                         cudaFuncAttributeMaxDynamicSharedMemorySize, GEMM_SMEM);

    // 0) fused bf16 operand prep (single launch)
    prep_kernel<<<4288, 256>>>(x, xb, w, wb, Wg, WgTb);

    // 1+2) merged: QK = xb @ wb^T + bias  AND  yT[b] = WgT @ x[b]^T
    bgemm_qkyt<<<768, 256, GEMM_SMEM>>>(m_xb, m_wb, m_WgTb, QKb, yT, bia);

    // 3) S: heads-as-chunks pipelined scores (fp16 raw, scaled 0.125)
    bgemm_scores<<<dim3(16, 16, NB), 256, SC_SMEM>>>(m_QKb, S);

    // 4) Bm[b,i,:] = mean_h softmax(S[b,h,i,:])
    pmean_kernel<<<NB * NL, 256>>>(S, Bmb);

    // 5) out[b] = Bm[b] @ yT[b]^T + Bg   [2048 x 256] x8, K=2048 (nk=32)
    bgemm<float, true><<<dim3(2, 16, NB), 256, GEMM_SMEM>>>(
        m_Bmb, m_yT,
        NL, 0, 0,   NE, 0, 0,
        out, NE, (long)NL * NE,
        1, NL / 64, 1.f, Bg);
}

// round 17
// speedup vs baseline: 1.1850x; 1.0079x over previous
#include <cuda_runtime.h>
#include <cuda.h>
#include <cuda_bf16.h>
#include <cuda_fp16.h>
#include <cstdint>

#define NB 8
#define NL 2048
#define NE 256
#define NH 4
#define ND 64

// ---------------- scratch (device globals; no allocation allowed) -----------
__device__ __nv_bfloat16 g_xb  [(size_t)NB * NL * NE];        // bf16 x
__device__ __nv_bfloat16 g_wb  [(size_t)2 * NE * NE];         // bf16 w[0:512]
__device__ __nv_bfloat16 g_WgTb[(size_t)NE * NE];             // bf16 Wg^T
__device__ __nv_bfloat16 g_QKb [(size_t)NB * NL * 2 * NE];    // [16384, 512]
__device__ __half        g_S   [(size_t)NB * NH * NL * NL];   // raw scores fp16
__device__ __nv_bfloat16 g_Bmb [(size_t)NB * NL * NL];        // head-mean probs
__device__ __nv_bfloat16 g_yT  [(size_t)NB * NE * NL];        // (x @ Wg)^T per b

// ------------------------------- helpers ------------------------------------
__device__ __forceinline__ uint32_t smem_u32(const void* p) {
    uint32_t a;
    asm("{ .reg .u64 t; cvta.to.shared.u64 t, %1; cvt.u32.u64 %0, t; }"
        : "=r"(a) : "l"(p));
    return a;
}

#define MBARRIER_INIT(addr, cnt) \
    asm volatile("mbarrier.init.shared.b64 [%0], %1;" :: "r"(addr), "r"(cnt) : "memory")

#define MBARRIER_EXPECT_TX(addr, bytes) \
    asm volatile("mbarrier.arrive.expect_tx.shared.b64 _, [%0], %1;" \
                 :: "r"(addr), "r"(bytes) : "memory")

#define MBARRIER_WAIT_PARITY(addr, par) do {                                   \
    uint32_t _m = (addr), _p = (par), _d;                                      \
    asm volatile("{\n\t.reg .pred p;\n\t"                                      \
        "mbarrier.try_wait.parity.acquire.cta.shared::cta.b64 p, [%1], %2;\n\t"\
        "selp.b32 %0, 1, 0, p;\n\t}"                                           \
        : "=r"(_d) : "r"(_m), "r"(_p) : "memory");                             \
    if (!_d) {                                                                 \
        asm volatile("{\n\t.reg .pred P1;\n\t"                                 \
        "WL_%=:\n\t"                                                           \
        "mbarrier.try_wait.parity.acquire.cta.shared::cta.b64 P1, [%0], %1, 0x989680;\n\t" \
        "@P1 bra.uni WD_%=;\n\t"                                               \
        "bra.uni WL_%=;\n\t"                                                   \
        "WD_%=:\n\t}" :: "r"(_m), "r"(_p) : "memory");                         \
    }                                                                          \
} while (0)

#define TMA_LOAD_2D(saddr, tmap, cx, cy, mbar)                                 \
    asm volatile("cp.async.bulk.tensor.2d.shared::cta.global.tile.mbarrier::complete_tx::bytes " \
        "[%0], [%1, {%2, %3}], [%4];"                                          \
        :: "r"((uint32_t)(saddr)), "l"(tmap), "r"((int)(cx)), "r"((int)(cy)),  \
           "r"((uint32_t)(mbar)) : "memory")

#define FENCE_ASYNC_SHARED() asm volatile("fence.proxy.async.shared::cta;" ::: "memory")

#define MMA_BF16(d, a, b)                                                      \
    asm volatile("mma.sync.aligned.m16n8k16.row.col.f32.bf16.bf16.f32 "       \
        "{%0,%1,%2,%3}, {%4,%5,%6,%7}, {%8,%9}, {%0,%1,%2,%3};"                \
        : "+f"((d)[0]), "+f"((d)[1]), "+f"((d)[2]), "+f"((d)[3])               \
        : "r"((a)[0]), "r"((a)[1]), "r"((a)[2]), "r"((a)[3]),                  \
          "r"((b)[0]), "r"((b)[1]))

#define LDSM_X4(r0, r1, r2, r3, addr)                                          \
    asm volatile("ldmatrix.sync.aligned.m8n8.x4.shared.b16 {%0,%1,%2,%3}, [%4];" \
        : "=r"(r0), "=r"(r1), "=r"(r2), "=r"(r3) : "r"(addr))

__device__ __forceinline__ void store2(float* p, float a, float b) {
    *(float2*)p = make_float2(a, b);
}
__device__ __forceinline__ void store2(__nv_bfloat16* p, float a, float b) {
    *(__nv_bfloat162*)p = __floats2bfloat162_rn(a, b);
}
__device__ __forceinline__ void store2(__half* p, float a, float b) {
    *(__half2*)p = __floats2half2_rn(a, b);
}

#define STAGES     3
#define STG_BYTES  32768          // A 16KB + B 16KB, dense SW128 tiles
#define GEMM_SMEM  (STAGES * STG_BYTES + 1024 + 64)
// scores kernel: 2 stages + dedicated fp16 bounce (128 x 136)
#define SC_STAGES  2
#define SC_BOUNCE  (128 * 136 * 2)
#define SC_SMEM    (SC_STAGES * STG_BYTES + SC_BOUNCE + 1024 + 64)

struct Frag { float acc[4][4][4]; };

// one k16 x (4x4) fragment compute step from SW128 tiles
__device__ __forceinline__ void mma_step(
    uint32_t sA, uint32_t sB, int j,
    uint32_t aRow, uint32_t aCol0, uint32_t bRow, uint32_t bCol0, uint32_t xorv,
    Frag& F)
{
    uint32_t af[4][4], bf[4][2];
    const uint32_t ac = (aCol0 + j * 32) ^ xorv;
    const uint32_t bc = (bCol0 + j * 32) ^ xorv;
#pragma unroll
    for (int mt = 0; mt < 4; mt++)
        LDSM_X4(af[mt][0], af[mt][1], af[mt][2], af[mt][3],
                sA + aRow + mt * 2048 + ac);
#pragma unroll
    for (int p = 0; p < 2; p++)
        LDSM_X4(bf[2 * p][0], bf[2 * p][1], bf[2 * p + 1][0], bf[2 * p + 1][1],
                sB + bRow + p * 2048 + bc);
#pragma unroll
    for (int mt = 0; mt < 4; mt++)
#pragma unroll
        for (int nt = 0; nt < 4; nt++)
            MMA_BF16(F.acc[mt][nt], af[mt], bf[nt]);
}

__device__ __forceinline__ void gemm_mainloop(
    uint32_t sal, uint32_t mbb, int tid,
    const CUtensorMap* pA, const CUtensorMap* pB,
    int ary, int acx, int bry, int bcx, int nk,
    uint32_t aRow, uint32_t aCol0, uint32_t bRow, uint32_t bCol0, uint32_t xorv,
    Frag& F)
{
#pragma unroll
    for (int m = 0; m < 4; m++)
#pragma unroll
        for (int n = 0; n < 4; n++)
#pragma unroll
            for (int c = 0; c < 4; c++) F.acc[m][n][c] = 0.f;

    auto issue = [&](int chunk) {
        const int s = chunk % STAGES;
        MBARRIER_EXPECT_TX(mbb + s * 8, (uint32_t)STG_BYTES);
        TMA_LOAD_2D(sal + s * STG_BYTES,         pA, acx + chunk * 64, ary, mbb + s * 8);
        TMA_LOAD_2D(sal + s * STG_BYTES + 16384, pB, bcx + chunk * 64, bry, mbb + s * 8);
    };

    if (tid == 0) {
        issue(0);
        if (nk > 1) issue(1);
    }

    for (int i = 0; i < nk; i++) {
        const int s  = i % STAGES;
        const int ph = (i / STAGES) & 1;

        __syncthreads();
        if (tid == 0 && i + 2 < nk) issue(i + 2);
        MBARRIER_WAIT_PARITY(mbb + s * 8, ph);

        const uint32_t sA = sal + s * STG_BYTES;
        const uint32_t sB = sA + 16384;
#pragma unroll
        for (int j = 0; j < 4; j++)
            mma_step(sA, sB, j, aRow, aCol0, bRow, bCol0, xorv, F);
    }
}

// 16-bit-output epilogue: smem bounce -> coalesced 16B stores
template <typename OutT>
__device__ __forceinline__ void epilogue16(
    char* bounce, int tid, int wr, int wc, int g, int tg,
    OutT* Cz, int ldc, long crow0, int ccol0,
    float alpha, const float* bias, const Frag& F)
{
    OutT* Sb = (OutT*)bounce;            // 128 x 136 halfword
#pragma unroll
    for (int mt = 0; mt < 4; mt++) {
#pragma unroll
        for (int nt = 0; nt < 4; nt++) {
            const int r = wr + mt * 16 + g;
            const int c = wc + nt * 8 + tg * 2;
            float b0 = 0.f, b1 = 0.f;
            if (bias) { b0 = bias[ccol0 + c]; b1 = bias[ccol0 + c + 1]; }
            store2(Sb + (long)r * 136 + c,
                   F.acc[mt][nt][0] * alpha + b0, F.acc[mt][nt][1] * alpha + b1);
            store2(Sb + (long)(r + 8) * 136 + c,
                   F.acc[mt][nt][2] * alpha + b0, F.acc[mt][nt][3] * alpha + b1);
        }
    }
    __syncthreads();
#pragma unroll
    for (int it = 0; it < 8; it++) {
        const int idx = it * 256 + tid;
        const int row = idx >> 4;
        const int c16 = idx & 15;
        float4 v = *(float4*)(Sb + (long)row * 136 + c16 * 8);
        *(float4*)(Cz + (crow0 + row) * ldc + ccol0 + c16 * 8) = v;
    }
}

// ------------------------- generic batched GEMM ------------------------------
template <typename OutT, bool HAS_BIAS>
__global__ __launch_bounds__(256, 2)
void bgemm(const __grid_constant__ CUtensorMap tmA,
           const __grid_constant__ CUtensorMap tmB,
           int a_zo_row, int a_zi_col, int a_col_base,
           int b_zo_row, int b_zi_col, int b_col_base,
           OutT* __restrict__ C, int ldc, long sC,
           int inner, int nk, float alpha, const float* __restrict__ bias)
{
    extern __shared__ char smem[];
    const uint32_t sb0 = smem_u32(smem);
    const uint32_t sal = (sb0 + 1023) & ~1023u;
    const uint32_t mbb = sal + STAGES * STG_BYTES;

    const int tid    = threadIdx.x;
    const int warpId = tid >> 5;
    const int lane   = tid & 31;
    const int g  = lane >> 2;
    const int tg = lane & 3;
    const int wr = (warpId & 1) * 64;
    const int wc = (warpId >> 1) * 32;

    const int z  = blockIdx.z;
    const int zo = z / inner;
    const int zi = z - zo * inner;

    const int ary = zo * a_zo_row + blockIdx.y * 128;
    const int acx = a_col_base + zi * a_zi_col;
    const int bry = zo * b_zo_row + blockIdx.x * 128;
    const int bcx = b_col_base + zi * b_zi_col;

    if (tid == 0) {
#pragma unroll
        for (int s = 0; s < STAGES; s++) MBARRIER_INIT(mbb + s * 8, 1);
        FENCE_ASYNC_SHARED();
    }
    __syncthreads();

    const uint32_t xorv  = (uint32_t)((lane & 7) << 4);
    const uint32_t aRow  = (uint32_t)(wr + (lane & 15)) * 128;
    const uint32_t aCol0 = (uint32_t)((lane >> 4) * 16);
    const uint32_t bRow  = (uint32_t)(wc + (lane & 7) + ((lane >> 4) << 3)) * 128;
    const uint32_t bCol0 = (uint32_t)(((lane >> 3) & 1) * 16);

    Frag F;
    gemm_mainloop(sal, mbb, tid, &tmA, &tmB, ary, acx, bry, bcx, nk,
                  aRow, aCol0, bRow, bCol0, xorv, F);

    __syncthreads();
    char* bounce = smem + (sal - sb0);
    OutT* Cz = C + (long)z * sC;
    const long crow0 = (long)blockIdx.y * 128;
    const int  ccol0 = blockIdx.x * 128;
    const float* bp = HAS_BIAS ? bias : nullptr;

    if (sizeof(OutT) == 2) {
        epilogue16(bounce, tid, wr, wc, g, tg, Cz, ldc, crow0, ccol0, alpha, bp, F);
    } else {
        float* Sb = (float*)bounce;      // 128 x 132 fp32
#pragma unroll
        for (int mt = 0; mt < 4; mt++) {
#pragma unroll
            for (int nt = 0; nt < 4; nt++) {
                const int r = wr + mt * 16 + g;
                const int c = wc + nt * 8 + tg * 2;
                float b0 = 0.f, b1 = 0.f;
                if (HAS_BIAS) { b0 = bias[ccol0 + c]; b1 = bias[ccol0 + c + 1]; }
                *(float2*)(Sb + (long)r * 132 + c) =
                    make_float2(F.acc[mt][nt][0] * alpha + b0, F.acc[mt][nt][1] * alpha + b1);
                *(float2*)(Sb + (long)(r + 8) * 132 + c) =
                    make_float2(F.acc[mt][nt][2] * alpha + b0, F.acc[mt][nt][3] * alpha + b1);
            }
        }
        __syncthreads();
#pragma unroll
        for (int it = 0; it < 16; it++) {
            const int idx = it * 256 + tid;
            const int row = idx >> 5;
            const int c4  = idx & 31;
            float4 v = *(float4*)(Sb + (long)row * 132 + c4 * 4);
            *(float4*)((float*)Cz + (crow0 + row) * ldc + ccol0 + c4 * 4) = v;
        }
    }
}

// ------------- merged QK + yT GEMM (both nk=4, bf16 out) --------------------
__global__ __launch_bounds__(256, 2)
void bgemm_qkyt(const __grid_constant__ CUtensorMap tmXb,
                const __grid_constant__ CUtensorMap tmWb,
                const __grid_constant__ CUtensorMap tmWgT,
                __nv_bfloat16* __restrict__ QKb,
                __nv_bfloat16* __restrict__ yT,
                const float* __restrict__ bia)
{
    extern __shared__ char smem[];
    const uint32_t sb0 = smem_u32(smem);
    const uint32_t sal = (sb0 + 1023) & ~1023u;
    const uint32_t mbb = sal + STAGES * STG_BYTES;

    const int tid    = threadIdx.x;
    const int warpId = tid >> 5;
    const int lane   = tid & 31;
    const int g  = lane >> 2;
    const int tg = lane & 3;
    const int wr = (warpId & 1) * 64;
    const int wc = (warpId >> 1) * 32;

    const int id = blockIdx.x;
    const bool isQK = (id < 512);
    int xt, yt, zb;
    if (isQK) { xt = id & 3;  yt = id >> 2;        zb = 0; }
    else      { int t = id - 512; xt = t & 15; yt = (t >> 4) & 1; zb = t >> 5; }

    const CUtensorMap* pA = isQK ? &tmXb : &tmWgT;
    const CUtensorMap* pB = isQK ? &tmWb : &tmXb;
    const int ary = yt * 128;
    const int bry = (isQK ? 0 : zb * NL) + xt * 128;

    __nv_bfloat16* Cz = isQK ? QKb : (yT + (long)zb * NE * NL);
    const int   ldc   = isQK ? (2 * NE) : NL;
    const float* bias = isQK ? bia : nullptr;

    if (tid == 0) {
#pragma unroll
        for (int s = 0; s < STAGES; s++) MBARRIER_INIT(mbb + s * 8, 1);
        FENCE_ASYNC_SHARED();
    }
    __syncthreads();

    const uint32_t xorv  = (uint32_t)((lane & 7) << 4);
    const uint32_t aRow  = (uint32_t)(wr + (lane & 15)) * 128;
    const uint32_t aCol0 = (uint32_t)((lane >> 4) * 16);
    const uint32_t bRow  = (uint32_t)(wc + (lane & 7) + ((lane >> 4) << 3)) * 128;
    const uint32_t bCol0 = (uint32_t)(((lane >> 3) & 1) * 16);

    Frag F;
    gemm_mainloop(sal, mbb, tid, pA, pB, ary, 0, bry, 0, NE / 64,
                  aRow, aCol0, bRow, bCol0, xorv, F);

    __syncthreads();
    char* bounce = smem + (sal - sb0);
    epilogue16(bounce, tid, wr, wc, g, tg, Cz, ldc,
               (long)yt * 128, xt * 128, 1.f, bias, F);
}

// ------------------ scores GEMM: heads-as-chunks (nk=4) ----------------------
__global__ __launch_bounds__(256, 2)
void bgemm_scores(const __grid_constant__ CUtensorMap tmQK,
                  __half* __restrict__ S)
{
    extern __shared__ char smem[];
    const uint32_t sb0 = smem_u32(smem);
    const uint32_t sal = (sb0 + 1023) & ~1023u;
    const uint32_t bnc = sal + SC_STAGES * STG_BYTES;
    const uint32_t mbb = bnc + SC_BOUNCE;
    char* bounce = smem + (bnc - sb0);

    const int tid    = threadIdx.x;
    const int warpId = tid >> 5;
    const int lane   = tid & 31;
    const int g  = lane >> 2;
    const int tg = lane & 3;
    const int wr = (warpId & 1) * 64;
    const int wc = (warpId >> 1) * 32;

    const int b  = blockIdx.z;
    const int i0 = blockIdx.y * 128;
    const int j0 = blockIdx.x * 128;
    const int ary = b * NL + i0;
    const int bry = b * NL + j0;

    if (tid == 0) {
#pragma unroll
        for (int s = 0; s < SC_STAGES; s++) MBARRIER_INIT(mbb + s * 8, 1);
        FENCE_ASYNC_SHARED();
    }
    __syncthreads();

    auto issue = [&](int h) {
        const int s = h & 1;
        MBARRIER_EXPECT_TX(mbb + s * 8, (uint32_t)STG_BYTES);
        TMA_LOAD_2D(sal + s * STG_BYTES,         &tmQK, h * 64,       ary, mbb + s * 8);
        TMA_LOAD_2D(sal + s * STG_BYTES + 16384, &tmQK, 256 + h * 64, bry, mbb + s * 8);
    };

    if (tid == 0) { issue(0); issue(1); }

    const uint32_t xorv  = (uint32_t)((lane & 7) << 4);
    const uint32_t aRow  = (uint32_t)(wr + (lane & 15)) * 128;
    const uint32_t aCol0 = (uint32_t)((lane >> 4) * 16);
    const uint32_t bRow  = (uint32_t)(wc + (lane & 7) + ((lane >> 4) << 3)) * 128;
    const uint32_t bCol0 = (uint32_t)(((lane >> 3) & 1) * 16);

    for (int h = 0; h < NH; h++) {
        const int s  = h & 1;
        const int ph = (h >> 1) & 1;
        MBARRIER_WAIT_PARITY(mbb + s * 8, ph);

        Frag F;
#pragma unroll
        for (int m = 0; m < 4; m++)
#pragma unroll
            for (int n = 0; n < 4; n++)
#pragma unroll
                for (int c = 0; c < 4; c++) F.acc[m][n][c] = 0.f;

        const uint32_t sA = sal + s * STG_BYTES;
        const uint32_t sB = sA + 16384;
#pragma unroll
        for (int j = 0; j < 4; j++)
            mma_step(sA, sB, j, aRow, aCol0, bRow, bCol0, xorv, F);

        __syncthreads();
        if (tid == 0 && h + 2 < NH) issue(h + 2);

        __half* Cz = S + ((long)(b * NH + h) * NL + i0) * NL;
        epilogue16(bounce, tid, wr, wc, g, tg, Cz, NL,
                   0L, j0, 0.125f, (const float*)nullptr, F);
        __syncthreads();
    }
}

// ---------------------------------------------------------------------------
// head-mean softmax from raw fp16 scores; packed f16x2 math (h2exp / hadd2 /
// hfma2), fp32 only at the cross-thread rowsum reduction. Accumulators carry
// a x16 scale to stay clear of fp16 denormals; removed at the bf16 store.
__global__ __launch_bounds__(256)
void pmean_kernel(const __half* __restrict__ S, __nv_bfloat16* __restrict__ Bm)
{
    __shared__ float red[8][4];
    const int bi   = blockIdx.x;
    const int b    = bi >> 11;
    const int i    = bi & 2047;
    const int tid  = threadIdx.x;
    const int wid  = tid >> 5;
    const int lane = tid & 31;

    const __half* base = S + ((long)b * NH * NL + i) * NL + tid * 8;

    union F4H { float4 f; __half2 hh[4]; } u[NH];
#pragma unroll
    for (int h = 0; h < NH; h++)
        u[h].f = __ldcs((const float4*)(base + (long)h * NL * NL));

    __half2 e[NH][4];
    float s[NH];
#pragma unroll
    for (int h = 0; h < NH; h++) {
#pragma unroll
        for (int j = 0; j < 4; j++)
            e[h][j] = h2exp(u[h].hh[j]);
        __half2 t01 = __hadd2(e[h][0], e[h][1]);
        __half2 t23 = __hadd2(e[h][2], e[h][3]);
        __half2 tt  = __hadd2(t01, t23);
        float2 tf = __half22float2(tt);
        float sum = tf.x + tf.y;
#pragma unroll
        for (int o = 16; o; o >>= 1)
            sum += __shfl_xor_sync(0xffffffffu, sum, o);
        s[h] = sum;
    }
    if (lane < 4) red[wid][lane] = s[lane];
    __syncthreads();

    __half2 inv2[NH];
#pragma unroll
    for (int h = 0; h < NH; h++) {
        float st = red[0][h];
#pragma unroll
        for (int w = 1; w < 8; w++) st += red[w][h];
        inv2[h] = __float2half2_rn(4.0f / st);   // 16 * (0.25 / st)
    }

    __half2 acc[4];
#pragma unroll
    for (int j = 0; j < 4; j++)
        acc[j] = __hmul2(e[0][j], inv2[0]);
#pragma unroll
    for (int h = 1; h < NH; h++)
#pragma unroll
        for (int j = 0; j < 4; j++)
            acc[j] = __hfma2(e[h][j], inv2[h], acc[j]);

    union { float4 f; __nv_bfloat162 hh[4]; } o;
#pragma unroll
    for (int j = 0; j < 4; j++) {
        float2 p = __half22float2(acc[j]);
        o.hh[j] = __floats2bfloat162_rn(p.x * 0.0625f, p.y * 0.0625f);
    }
    *(float4*)(Bm + (long)bi * NL + tid * 8) = o.f;
}

// ---------------------------------------------------------------------------
// fused prep: one launch covering x-convert, w-convert, WgT transpose.
__global__ __launch_bounds__(256)
void prep_kernel(const float* __restrict__ x,  __nv_bfloat16* __restrict__ xb,
                 const float* __restrict__ w,  __nv_bfloat16* __restrict__ wb,
                 const float* __restrict__ Wg, __nv_bfloat16* __restrict__ WgTb)
{
    __shared__ float t[32][33];
    const int id  = blockIdx.x;
    const int tid = threadIdx.x;

    if (id < 4096) {
        const long i = ((long)id * 256 + tid) * 4;
        float4 v = *(const float4*)(x + i);
        union { uint2 u; __nv_bfloat162 h[2]; } p;
        p.h[0] = __floats2bfloat162_rn(v.x, v.y);
        p.h[1] = __floats2bfloat162_rn(v.z, v.w);
        *(uint2*)(xb + i) = p.u;
    } else if (id < 4224) {
        const long i = ((long)(id - 4096) * 256 + tid) * 4;
        float4 v = *(const float4*)(w + i);
        union { uint2 u; __nv_bfloat162 h[2]; } p;
        p.h[0] = __floats2bfloat162_rn(v.x, v.y);
        p.h[1] = __floats2bfloat162_rn(v.z, v.w);
        *(uint2*)(wb + i) = p.u;
    } else {
        const int bidx = id - 4224;
        const int c0 = (bidx & 7) * 32;
        const int r0 = (bidx >> 3) * 32;
        const int xx = tid & 31, yy = tid >> 5;
#pragma unroll
        for (int i = 0; i < 32; i += 8)
            t[yy + i][xx] = Wg[(long)(r0 + yy + i) * NE + c0 + xx];
        __syncthreads();
#pragma unroll
        for (int i = 0; i < 32; i += 8)
            WgTb[(long)(c0 + yy + i) * NE + r0 + xx] = __float2bfloat16_rn(t[xx][yy + i]);
    }
}

// ---------------------------------------------------------------------------
typedef CUresult (*encode_fn_t)(
    CUtensorMap*, CUtensorMapDataType, cuuint32_t, void*,
    const cuuint64_t*, const cuuint64_t*, const cuuint32_t*, const cuuint32_t*,
    CUtensorMapInterleave, CUtensorMapSwizzle, CUtensorMapL2promotion,
    CUtensorMapFloatOOBfill);

static void make_map(encode_fn_t enc, CUtensorMap* m, void* ptr, long rows, long cols)
{
    cuuint64_t dims[2]    = {(cuuint64_t)cols, (cuuint64_t)rows};
    cuuint64_t strides[1] = {(cuuint64_t)cols * 2};
    cuuint32_t box[2]     = {64u, 128u};
    cuuint32_t es[2]      = {1u, 1u};
    enc(m, CU_TENSOR_MAP_DATA_TYPE_BFLOAT16, 2, ptr, dims, strides, box, es,
        CU_TENSOR_MAP_INTERLEAVE_NONE, CU_TENSOR_MAP_SWIZZLE_128B,
        CU_TENSOR_MAP_L2_PROMOTION_L2_128B, CU_TENSOR_MAP_FLOAT_OOB_FILL_NONE);
}

extern "C" void kernel_launch(void* const* d_in, const int* in_sizes, int n_in,
                              void* d_out, int out_size)
{
    (void)in_sizes; (void)n_in; (void)out_size;
    const float* x   = (const float*)d_in[0];
    const float* w   = (const float*)d_in[1];
    const float* bia = (const float*)d_in[2];
    const float* Wg  = (const float*)d_in[3];
    const float* Bg  = (const float*)d_in[4];
    float* out = (float*)d_out;

    __nv_bfloat16 *xb, *wb, *WgTb, *QKb, *Bmb, *yT;
    __half* S;
    cudaGetSymbolAddress((void**)&xb,   g_xb);
    cudaGetSymbolAddress((void**)&wb,   g_wb);
    cudaGetSymbolAddress((void**)&WgTb, g_WgTb);
    cudaGetSymbolAddress((void**)&QKb,  g_QKb);
    cudaGetSymbolAddress((void**)&S,    g_S);
    cudaGetSymbolAddress((void**)&Bmb,  g_Bmb);
    cudaGetSymbolAddress((void**)&yT,   g_yT);

    encode_fn_t enc = nullptr;
    {
        void* p = nullptr;
        cudaDriverEntryPointQueryResult st;
        cudaGetDriverEntryPoint("cuTensorMapEncodeTiled", &p, cudaEnableDefault, &st);
        enc = (encode_fn_t)p;
    }

    CUtensorMap m_xb, m_wb, m_WgTb, m_QKb, m_Bmb, m_yT;
    make_map(enc, &m_xb,   xb,   (long)NB * NL, NE);
    make_map(enc, &m_wb,   wb,   2 * NE,        NE);
    make_map(enc, &m_WgTb, WgTb, NE,            NE);
    make_map(enc, &m_QKb,  QKb,  (long)NB * NL, 2 * NE);
    make_map(enc, &m_Bmb,  Bmb,  (long)NB * NL, NL);
    make_map(enc, &m_yT,   yT,   (long)NB * NE, NL);

    cudaFuncSetAttribute((const void*)bgemm_qkyt,
                         cudaFuncAttributeMaxDynamicSharedMemorySize, GEMM_SMEM);
    cudaFuncSetAttribute((const void*)bgemm_scores,
                         cudaFuncAttributeMaxDynamicSharedMemorySize, SC_SMEM);
    cudaFuncSetAttribute((const void*)bgemm<float, true>,
                         cudaFuncAttributeMaxDynamicSharedMemorySize, GEMM_SMEM);

    // 0) fused bf16 operand prep (single launch)
    prep_kernel<<<4288, 256>>>(x, xb, w, wb, Wg, WgTb);

    // 1+2) merged: QK = xb @ wb^T + bias  AND  yT[b] = WgT @ x[b]^T
    bgemm_qkyt<<<768, 256, GEMM_SMEM>>>(m_xb, m_wb, m_WgTb, QKb, yT, bia);

    // 3) S: heads-as-chunks pipelined scores (fp16 raw, scaled 0.125)
    bgemm_scores<<<dim3(16, 16, NB), 256, SC_SMEM>>>(m_QKb, S);

    // 4) Bm[b,i,:] = mean_h softmax(S[b,h,i,:])   (f16x2 math)
    pmean_kernel<<<NB * NL, 256>>>(S, Bmb);

    // 5) out[b] = Bm[b] @ yT[b]^T + Bg   [2048 x 256] x8, K=2048 (nk=32)
    bgemm<float, true><<<dim3(2, 16, NB), 256, GEMM_SMEM>>>(
        m_Bmb, m_yT,
        NL, 0, 0,   NE, 0, 0,
        out, NE, (long)NL * NE,
        1, NL / 64, 1.f, Bg);
}